// round 13
// baseline (speedup 1.0000x reference)
#include <cuda_runtime.h>
#include <cuda_fp16.h>
#include <cstdint>
#include <cstddef>

// ============================================================================
// FP4SymmetricLinear: C[8192,4096] = X[8192,4096] @ W^T[4096,4096] + bias
//
// compute_103 toolchain (no tcgen05). HMMA mma.sync path:
//   1) convert_x: fp32 -> fp16 scratch (g_x16)
//   2) dequant_w: packed fp4 codebook -> fp16 weights (g_w16)
//   3) GEMM: 128x128 CTA tile, 4 warps (2Mx2N), warp tile 64x64, BK=64,
//      TWO-stage double-buffered cp.async (73.7KB SMEM/CTA -> 2 CTAs/SM),
//      one __syncthreads per 64-wide K step (64 iters vs 128),
//      register double-buffered ldmatrix, mma.sync.m16n8k16 fp32 accum.
// ============================================================================

#define M_TOTAL 8192
#define N_TOTAL 4096
#define K_TOTAL 4096

#define BM 128
#define BN 128
#define BK 64
#define KITERS (K_TOTAL / BK)       // 64
#define STAGES 2
#define THREADS 128

// SMEM rows padded to 72 halves (144B). Row stride = 36 words; consecutive
// rows step 4 banks -> ldmatrix 8-row groups and STS.128 are conflict-free.
#define ROW_BYTES   144
#define A_TILE_SMEM (BM * ROW_BYTES)             // 18432
#define B_TILE_SMEM (BN * ROW_BYTES)             // 18432
#define STAGE_SMEM  (A_TILE_SMEM + B_TILE_SMEM)  // 36864
#define SMEM_TOTAL  (STAGES * STAGE_SMEM)        // 73728 (x2 CTAs = 147456)

// Scratch (device globals: allocation-free rule compliant)
__device__ __align__(16) __half g_x16[(size_t)M_TOTAL * K_TOTAL];
__device__ __align__(16) __half g_w16[(size_t)N_TOTAL * K_TOTAL];

__device__ __constant__ float c_codebook[16] = {
    0.0f, 0.0052f, 0.6667f, 1.0f, 0.3333f, 0.5f, 0.1667f, 0.25f,
    0.0f, -0.0052f, -0.6667f, -1.0f, -0.3333f, -0.5f, -0.1667f, -0.25f
};

// ---------------------------------------------------------------------------
// PTX helpers (compute_80-era instructions only — valid at compute_103)
// ---------------------------------------------------------------------------
__device__ __forceinline__ uint32_t smem_to_u32(const void* smem_ptr) {
    uint32_t addr;
    asm("{ .reg .u64 tmp; cvta.to.shared.u64 tmp, %1; cvt.u32.u64 %0, tmp; }"
        : "=r"(addr) : "l"(smem_ptr));
    return addr;
}

#define CP_ASYNC_CG(saddr, gptr) \
    asm volatile("cp.async.cg.shared.global [%0], [%1], 16;" \
                 :: "r"(saddr), "l"(gptr) : "memory")
#define CP_COMMIT() \
    asm volatile("cp.async.commit_group;" ::: "memory")
#define CP_WAIT(n) \
    asm volatile("cp.async.wait_group %0;" :: "n"(n) : "memory")

#define LDMATRIX_X4(r0, r1, r2, r3, addr) \
    asm volatile("ldmatrix.sync.aligned.m8n8.x4.shared.b16 {%0,%1,%2,%3}, [%4];" \
                 : "=r"(r0), "=r"(r1), "=r"(r2), "=r"(r3) : "r"(addr))

#define MMA16816(d, a, b) \
    asm volatile("mma.sync.aligned.m16n8k16.row.col.f32.f16.f16.f32 " \
                 "{%0,%1,%2,%3}, {%4,%5,%6,%7}, {%8,%9}, {%0,%1,%2,%3};" \
                 : "+f"((d)[0]), "+f"((d)[1]), "+f"((d)[2]), "+f"((d)[3]) \
                 : "r"((a)[0]), "r"((a)[1]), "r"((a)[2]), "r"((a)[3]), \
                   "r"((b)[0]), "r"((b)[1]))

// ---------------------------------------------------------------------------
// Prepass 1: x fp32 -> fp16 (8 elements per thread)
// ---------------------------------------------------------------------------
__global__ void __launch_bounds__(256) convert_x_kernel(const float4* __restrict__ x4) {
    size_t i = (size_t)blockIdx.x * 256 + threadIdx.x;   // 4,194,304 threads
    float4 a = x4[2 * i];
    float4 b = x4[2 * i + 1];
    union { uint4 u; __half2 h[4]; } t;
    t.h[0] = __floats2half2_rn(a.x, a.y);
    t.h[1] = __floats2half2_rn(a.z, a.w);
    t.h[2] = __floats2half2_rn(b.x, b.y);
    t.h[3] = __floats2half2_rn(b.z, b.w);
    ((uint4*)g_x16)[i] = t.u;
}

// ---------------------------------------------------------------------------
// Prepass 2: dequant packed fp4 -> fp16 (4 packed bytes -> 8 weights/thread)
// Element 2i = high nibble of byte i, element 2i+1 = low nibble.
// block(e) = e >> 6; 8 consecutive elements of an aligned thread share a block.
// ---------------------------------------------------------------------------
__global__ void __launch_bounds__(256) dequant_w_kernel(
    const int4* __restrict__ wp4, const float* __restrict__ scale
) {
    __shared__ float cb[16];
    if (threadIdx.x < 16) cb[threadIdx.x] = c_codebook[threadIdx.x];
    __syncthreads();

    size_t i = (size_t)blockIdx.x * 256 + threadIdx.x;   // 2,097,152 threads
    int4 p = wp4[i];
    float s = __ldg(scale + (i >> 3));
    union { uint4 u; __half h[8]; } t;
    t.h[0] = __float2half_rn(cb[(p.x >> 4) & 15] * s);
    t.h[1] = __float2half_rn(cb[p.x & 15] * s);
    t.h[2] = __float2half_rn(cb[(p.y >> 4) & 15] * s);
    t.h[3] = __float2half_rn(cb[p.y & 15] * s);
    t.h[4] = __float2half_rn(cb[(p.z >> 4) & 15] * s);
    t.h[5] = __float2half_rn(cb[p.z & 15] * s);
    t.h[6] = __float2half_rn(cb[(p.w >> 4) & 15] * s);
    t.h[7] = __float2half_rn(cb[p.w & 15] * s);
    ((uint4*)g_w16)[i] = t.u;
}

// ---------------------------------------------------------------------------
// GEMM kernel
// 4 warps: 2 (M) x 2 (N); warp tile 64x64; per-thread 4x8 m16n8 accumulators.
// BK=64 (4 k16 chunks), 2-stage SMEM double buffer, 1 sync per iteration.
// ---------------------------------------------------------------------------
__global__ void __launch_bounds__(THREADS, 2) gemm_kernel(
    float* __restrict__ out, const float* __restrict__ bias
) {
    extern __shared__ char smem[];
    uint32_t smem_u32 = smem_to_u32(smem);
    int tid  = threadIdx.x;
    int wid  = tid >> 5;
    int lane = tid & 31;
    int wm   = wid & 1;          // warp row 0..1 (64 M-rows each)
    int wn   = wid >> 1;         // warp col 0..1 (64 N-cols each)

    // Rasterize: supertiles of 8 M-tiles x all 32 N-tiles for L2 reuse
    int pid = blockIdx.x;                 // 0..2047
    int g   = pid >> 8;                   // 8 groups
    int rem = pid & 255;
    int mt  = (g << 3) + (rem & 7);       // 0..63
    int nt  = rem >> 3;                   // 0..31
    int m0  = mt * BM;
    int n0  = nt * BN;

    const __half* __restrict__ xA = g_x16 + (size_t)m0 * K_TOTAL;
    const __half* __restrict__ wB = g_w16 + (size_t)n0 * K_TOTAL;

    // Load coords: 16B chunks; tile = 128 rows x 8 chunks = 1024 chunks;
    // 8 chunks/thread per operand. Rows: lr + it*16.
    int lr = tid >> 3, lc = tid & 7;

    auto issue_stage = [&](int s) {
        int kpos = s * BK;
        uint32_t sbase = smem_u32 + (s & 1) * STAGE_SMEM;
        uint32_t bb = sbase + A_TILE_SMEM;
        #pragma unroll
        for (int it = 0; it < 8; ++it) {
            int r = lr + it * 16;
            CP_ASYNC_CG(sbase + r * ROW_BYTES + lc * 16,
                        xA + (size_t)r * K_TOTAL + kpos + lc * 8);
            CP_ASYNC_CG(bb + r * ROW_BYTES + lc * 16,
                        wB + (size_t)r * K_TOTAL + kpos + lc * 8);
        }
        CP_COMMIT();
    };

    float acc[4][8][4];
    #pragma unroll
    for (int i = 0; i < 4; ++i)
        #pragma unroll
        for (int j = 0; j < 8; ++j)
            #pragma unroll
            for (int k = 0; k < 4; ++k) acc[i][j][k] = 0.0f;

    issue_stage(0);

    // ldmatrix lane addressing
    int a_row_l  = lane & 15;              // row within 16x16 A tile
    int a_koff_l = (lane >> 4) * 8;        // k-half
    int b_mat    = lane >> 3;              // which 8x8 matrix
    int b_row_l  = (lane & 7) + ((b_mat >> 1) << 3);
    int b_koff_l = (b_mat & 1) * 8;

    uint32_t a[2][4][4];
    uint32_t b[2][8][2];

    for (int s = 0; s < KITERS; ++s) {
        // Stage s landed; sync also proves stage s-1's buffer is drained by
        // all warps, so we can refill it with stage s+1 below.
        CP_WAIT(0);
        __syncthreads();

        if (s + 1 < KITERS) issue_stage(s + 1);   // overlaps compute(s)

        uint32_t sbase = smem_u32 + (s & 1) * STAGE_SMEM;
        uint32_t aBase = sbase;
        uint32_t bBase = sbase + A_TILE_SMEM;

        // Load k16 chunk 0 into operand buffer 0
        #pragma unroll
        for (int mi = 0; mi < 4; ++mi) {
            int row = wm * 64 + mi * 16 + a_row_l;
            LDMATRIX_X4(a[0][mi][0], a[0][mi][1], a[0][mi][2], a[0][mi][3],
                        aBase + row * ROW_BYTES + a_koff_l * 2);
        }
        #pragma unroll
        for (int j = 0; j < 4; ++j) {
            int nrow = wn * 64 + j * 16 + b_row_l;
            LDMATRIX_X4(b[0][2 * j][0], b[0][2 * j][1],
                        b[0][2 * j + 1][0], b[0][2 * j + 1][1],
                        bBase + nrow * ROW_BYTES + b_koff_l * 2);
        }

        #pragma unroll
        for (int ks = 0; ks < 4; ++ks) {       // 4 x k16 per BK=64
            int cur = ks & 1, nxt = cur ^ 1;
            if (ks < 3) {
                int col = (ks + 1) * 16;
                #pragma unroll
                for (int mi = 0; mi < 4; ++mi) {
                    int row = wm * 64 + mi * 16 + a_row_l;
                    LDMATRIX_X4(a[nxt][mi][0], a[nxt][mi][1],
                                a[nxt][mi][2], a[nxt][mi][3],
                                aBase + row * ROW_BYTES + (col + a_koff_l) * 2);
                }
                #pragma unroll
                for (int j = 0; j < 4; ++j) {
                    int nrow = wn * 64 + j * 16 + b_row_l;
                    LDMATRIX_X4(b[nxt][2 * j][0], b[nxt][2 * j][1],
                                b[nxt][2 * j + 1][0], b[nxt][2 * j + 1][1],
                                bBase + nrow * ROW_BYTES + (col + b_koff_l) * 2);
                }
            }
            #pragma unroll
            for (int mi = 0; mi < 4; ++mi)
                #pragma unroll
                for (int nj = 0; nj < 8; ++nj)
                    MMA16816(acc[mi][nj], a[cur][mi], b[cur][nj]);
        }
    }

    // Epilogue: m16n8 D frag: d0,d1 -> row l>>2, cols 2(l&3)+{0,1};
    // d2,d3 -> row (l>>2)+8.
    int row_base = m0 + wm * 64 + (lane >> 2);
    int col_base = n0 + wn * 64 + (lane & 3) * 2;
    #pragma unroll
    for (int mi = 0; mi < 4; ++mi) {
        #pragma unroll
        for (int nj = 0; nj < 8; ++nj) {
            int c = col_base + nj * 8;
            float2 bv = *(const float2*)(bias + c);
            #pragma unroll
            for (int h = 0; h < 2; ++h) {
                int r = row_base + mi * 16 + h * 8;
                float2 o;
                o.x = acc[mi][nj][2 * h + 0] + bv.x;
                o.y = acc[mi][nj][2 * h + 1] + bv.y;
                *(float2*)(out + (size_t)r * N_TOTAL + c) = o;
            }
        }
    }
}

// ---------------------------------------------------------------------------
// Launch
// ---------------------------------------------------------------------------
extern "C" void kernel_launch(void* const* d_in, const int* in_sizes, int n_in,
                              void* d_out, int out_size) {
    const float* x     = (const float*)d_in[0];   // [4,2048,4096] fp32
    const int*   wp    = (const int*)d_in[1];     // [8388608] int32 (1 byte each)
    const float* scale = (const float*)d_in[2];   // [262144] fp32
    const float* bias  = (const float*)d_in[3];   // [4096] fp32
    float*       out   = (float*)d_out;           // [4,2048,4096] fp32

    (void)in_sizes; (void)n_in; (void)out_size;

    convert_x_kernel<<<16384, 256>>>((const float4*)x);
    dequant_w_kernel<<<8192, 256>>>((const int4*)wp, scale);

    cudaFuncSetAttribute(gemm_kernel,
                         cudaFuncAttributeMaxDynamicSharedMemorySize, SMEM_TOTAL);
    gemm_kernel<<<(M_TOTAL / BM) * (N_TOTAL / BN), THREADS, SMEM_TOTAL>>>(out, bias);
}

// round 14
// speedup vs baseline: 1.0090x; 1.0090x over previous
#include <cuda_runtime.h>
#include <cuda_fp16.h>
#include <cstdint>
#include <cstddef>

// ============================================================================
// FP4SymmetricLinear: C[8192,4096] = X[8192,4096] @ W^T[4096,4096] + bias
//
// compute_103 toolchain (no tcgen05). HMMA mma.sync path:
//   1) convert_x: fp32 -> fp16 scratch (g_x16)
//   2) dequant_w: packed fp4 codebook -> fp16 weights (g_w16)
//   3) GEMM: 128x128 CTA tile, 4 warps (2Mx2N), warp tile 64x64, BK=64,
//      THREE-stage cp.async pipeline (depth-2 prefetch, CP_WAIT(1)),
//      single-buffered ldmatrix operands (~190 regs, no spill),
//      mma.sync.m16n8k16 fp32 accum, bias epilogue. 2 CTAs/SM.
// ============================================================================

#define M_TOTAL 8192
#define N_TOTAL 4096
#define K_TOTAL 4096

#define BM 128
#define BN 128
#define BK 64
#define KITERS (K_TOTAL / BK)       // 64
#define STAGES 3
#define THREADS 128

// SMEM rows padded to 72 halves (144B). Row stride = 36 words; consecutive
// rows step 4 banks -> ldmatrix 8-row groups and STS.128 are conflict-free.
#define ROW_BYTES   144
#define A_TILE_SMEM (BM * ROW_BYTES)             // 18432
#define B_TILE_SMEM (BN * ROW_BYTES)             // 18432
#define STAGE_SMEM  (A_TILE_SMEM + B_TILE_SMEM)  // 36864
#define SMEM_TOTAL  (STAGES * STAGE_SMEM)        // 110592 (x2 CTAs ~ 218KB)

// Scratch (device globals: allocation-free rule compliant)
__device__ __align__(16) __half g_x16[(size_t)M_TOTAL * K_TOTAL];
__device__ __align__(16) __half g_w16[(size_t)N_TOTAL * K_TOTAL];

__device__ __constant__ float c_codebook[16] = {
    0.0f, 0.0052f, 0.6667f, 1.0f, 0.3333f, 0.5f, 0.1667f, 0.25f,
    0.0f, -0.0052f, -0.6667f, -1.0f, -0.3333f, -0.5f, -0.1667f, -0.25f
};

// ---------------------------------------------------------------------------
// PTX helpers (compute_80-era instructions only — valid at compute_103)
// ---------------------------------------------------------------------------
__device__ __forceinline__ uint32_t smem_to_u32(const void* smem_ptr) {
    uint32_t addr;
    asm("{ .reg .u64 tmp; cvta.to.shared.u64 tmp, %1; cvt.u32.u64 %0, tmp; }"
        : "=r"(addr) : "l"(smem_ptr));
    return addr;
}

#define CP_ASYNC_CG(saddr, gptr) \
    asm volatile("cp.async.cg.shared.global [%0], [%1], 16;" \
                 :: "r"(saddr), "l"(gptr) : "memory")
#define CP_COMMIT() \
    asm volatile("cp.async.commit_group;" ::: "memory")
#define CP_WAIT(n) \
    asm volatile("cp.async.wait_group %0;" :: "n"(n) : "memory")

#define LDMATRIX_X4(r0, r1, r2, r3, addr) \
    asm volatile("ldmatrix.sync.aligned.m8n8.x4.shared.b16 {%0,%1,%2,%3}, [%4];" \
                 : "=r"(r0), "=r"(r1), "=r"(r2), "=r"(r3) : "r"(addr))

#define MMA16816(d, a, b) \
    asm volatile("mma.sync.aligned.m16n8k16.row.col.f32.f16.f16.f32 " \
                 "{%0,%1,%2,%3}, {%4,%5,%6,%7}, {%8,%9}, {%0,%1,%2,%3};" \
                 : "+f"((d)[0]), "+f"((d)[1]), "+f"((d)[2]), "+f"((d)[3]) \
                 : "r"((a)[0]), "r"((a)[1]), "r"((a)[2]), "r"((a)[3]), \
                   "r"((b)[0]), "r"((b)[1]))

// ---------------------------------------------------------------------------
// Prepass 1: x fp32 -> fp16 (8 elements per thread)
// ---------------------------------------------------------------------------
__global__ void __launch_bounds__(256) convert_x_kernel(const float4* __restrict__ x4) {
    size_t i = (size_t)blockIdx.x * 256 + threadIdx.x;   // 4,194,304 threads
    float4 a = x4[2 * i];
    float4 b = x4[2 * i + 1];
    union { uint4 u; __half2 h[4]; } t;
    t.h[0] = __floats2half2_rn(a.x, a.y);
    t.h[1] = __floats2half2_rn(a.z, a.w);
    t.h[2] = __floats2half2_rn(b.x, b.y);
    t.h[3] = __floats2half2_rn(b.z, b.w);
    ((uint4*)g_x16)[i] = t.u;
}

// ---------------------------------------------------------------------------
// Prepass 2: dequant packed fp4 -> fp16 (4 packed bytes -> 8 weights/thread)
// Element 2i = high nibble of byte i, element 2i+1 = low nibble.
// block(e) = e >> 6; 8 consecutive elements of an aligned thread share a block.
// ---------------------------------------------------------------------------
__global__ void __launch_bounds__(256) dequant_w_kernel(
    const int4* __restrict__ wp4, const float* __restrict__ scale
) {
    __shared__ float cb[16];
    if (threadIdx.x < 16) cb[threadIdx.x] = c_codebook[threadIdx.x];
    __syncthreads();

    size_t i = (size_t)blockIdx.x * 256 + threadIdx.x;   // 2,097,152 threads
    int4 p = wp4[i];
    float s = __ldg(scale + (i >> 3));
    union { uint4 u; __half h[8]; } t;
    t.h[0] = __float2half_rn(cb[(p.x >> 4) & 15] * s);
    t.h[1] = __float2half_rn(cb[p.x & 15] * s);
    t.h[2] = __float2half_rn(cb[(p.y >> 4) & 15] * s);
    t.h[3] = __float2half_rn(cb[p.y & 15] * s);
    t.h[4] = __float2half_rn(cb[(p.z >> 4) & 15] * s);
    t.h[5] = __float2half_rn(cb[p.z & 15] * s);
    t.h[6] = __float2half_rn(cb[(p.w >> 4) & 15] * s);
    t.h[7] = __float2half_rn(cb[p.w & 15] * s);
    ((uint4*)g_w16)[i] = t.u;
}

// ---------------------------------------------------------------------------
// GEMM kernel
// 4 warps: 2 (M) x 2 (N); warp tile 64x64; per-thread 4x8 m16n8 accumulators.
// BK=64 (4 k16 chunks), 3-stage SMEM pipeline, 1 sync per 64-wide K step.
// ---------------------------------------------------------------------------
__global__ void __launch_bounds__(THREADS, 2) gemm_kernel(
    float* __restrict__ out, const float* __restrict__ bias
) {
    extern __shared__ char smem[];
    uint32_t smem_u32 = smem_to_u32(smem);
    int tid  = threadIdx.x;
    int wid  = tid >> 5;
    int lane = tid & 31;
    int wm   = wid & 1;          // warp row 0..1 (64 M-rows each)
    int wn   = wid >> 1;         // warp col 0..1 (64 N-cols each)

    // Rasterize: supertiles of 8 M-tiles x all 32 N-tiles for L2 reuse
    int pid = blockIdx.x;                 // 0..2047
    int g   = pid >> 8;                   // 8 groups
    int rem = pid & 255;
    int mt  = (g << 3) + (rem & 7);       // 0..63
    int nt  = rem >> 3;                   // 0..31
    int m0  = mt * BM;
    int n0  = nt * BN;

    const __half* __restrict__ xA = g_x16 + (size_t)m0 * K_TOTAL;
    const __half* __restrict__ wB = g_w16 + (size_t)n0 * K_TOTAL;

    // Load coords: 16B chunks; tile = 128 rows x 8 chunks = 1024 chunks;
    // 8 chunks/thread per operand. Rows: lr + it*16.
    int lr = tid >> 3, lc = tid & 7;

    auto issue_stage = [&](int s) {
        int kpos = s * BK;
        uint32_t sbase = smem_u32 + (s % STAGES) * STAGE_SMEM;
        uint32_t bb = sbase + A_TILE_SMEM;
        #pragma unroll
        for (int it = 0; it < 8; ++it) {
            int r = lr + it * 16;
            CP_ASYNC_CG(sbase + r * ROW_BYTES + lc * 16,
                        xA + (size_t)r * K_TOTAL + kpos + lc * 8);
            CP_ASYNC_CG(bb + r * ROW_BYTES + lc * 16,
                        wB + (size_t)r * K_TOTAL + kpos + lc * 8);
        }
        CP_COMMIT();
    };

    float acc[4][8][4];
    #pragma unroll
    for (int i = 0; i < 4; ++i)
        #pragma unroll
        for (int j = 0; j < 8; ++j)
            #pragma unroll
            for (int k = 0; k < 4; ++k) acc[i][j][k] = 0.0f;

    issue_stage(0);
    issue_stage(1);

    // ldmatrix lane addressing
    int a_row_l  = lane & 15;              // row within 16x16 A tile
    int a_koff_l = (lane >> 4) * 8;        // k-half
    int b_mat    = lane >> 3;              // which 8x8 matrix
    int b_row_l  = (lane & 7) + ((b_mat >> 1) << 3);
    int b_koff_l = (b_mat & 1) * 8;

    for (int s = 0; s < KITERS; ++s) {
        // Wait for stage s (leaves <=1 group pending = stage s+1).
        CP_WAIT(1);
        __syncthreads();

        // Buffer (s+2)%3 == (s-1)%3 was fully consumed last iteration
        // (the sync above proves all warps are done with it) -> refill.
        if (s + 2 < KITERS) issue_stage(s + 2);
        else CP_COMMIT();   // keep wait_group counting aligned

        uint32_t sbase = smem_u32 + (s % STAGES) * STAGE_SMEM;
        uint32_t aBase = sbase;
        uint32_t bBase = sbase + A_TILE_SMEM;

        #pragma unroll
        for (int ks = 0; ks < 4; ++ks) {       // 4 x k16 per BK=64
            uint32_t a[4][4];
            uint32_t b[8][2];
            int col = ks * 16;
            #pragma unroll
            for (int mi = 0; mi < 4; ++mi) {
                int row = wm * 64 + mi * 16 + a_row_l;
                LDMATRIX_X4(a[mi][0], a[mi][1], a[mi][2], a[mi][3],
                            aBase + row * ROW_BYTES + (col + a_koff_l) * 2);
            }
            #pragma unroll
            for (int j = 0; j < 4; ++j) {
                int nrow = wn * 64 + j * 16 + b_row_l;
                LDMATRIX_X4(b[2 * j][0], b[2 * j][1],
                            b[2 * j + 1][0], b[2 * j + 1][1],
                            bBase + nrow * ROW_BYTES + (col + b_koff_l) * 2);
            }
            #pragma unroll
            for (int mi = 0; mi < 4; ++mi)
                #pragma unroll
                for (int nj = 0; nj < 8; ++nj)
                    MMA16816(acc[mi][nj], a[mi], b[nj]);
        }
    }

    // Epilogue: m16n8 D frag: d0,d1 -> row l>>2, cols 2(l&3)+{0,1};
    // d2,d3 -> row (l>>2)+8.
    int row_base = m0 + wm * 64 + (lane >> 2);
    int col_base = n0 + wn * 64 + (lane & 3) * 2;
    #pragma unroll
    for (int mi = 0; mi < 4; ++mi) {
        #pragma unroll
        for (int nj = 0; nj < 8; ++nj) {
            int c = col_base + nj * 8;
            float2 bv = *(const float2*)(bias + c);
            #pragma unroll
            for (int h = 0; h < 2; ++h) {
                int r = row_base + mi * 16 + h * 8;
                float2 o;
                o.x = acc[mi][nj][2 * h + 0] + bv.x;
                o.y = acc[mi][nj][2 * h + 1] + bv.y;
                *(float2*)(out + (size_t)r * N_TOTAL + c) = o;
            }
        }
    }
}

// ---------------------------------------------------------------------------
// Launch
// ---------------------------------------------------------------------------
extern "C" void kernel_launch(void* const* d_in, const int* in_sizes, int n_in,
                              void* d_out, int out_size) {
    const float* x     = (const float*)d_in[0];   // [4,2048,4096] fp32
    const int*   wp    = (const int*)d_in[1];     // [8388608] int32 (1 byte each)
    const float* scale = (const float*)d_in[2];   // [262144] fp32
    const float* bias  = (const float*)d_in[3];   // [4096] fp32
    float*       out   = (float*)d_out;           // [4,2048,4096] fp32

    (void)in_sizes; (void)n_in; (void)out_size;

    convert_x_kernel<<<16384, 256>>>((const float4*)x);
    dequant_w_kernel<<<8192, 256>>>((const int4*)wp, scale);

    cudaFuncSetAttribute(gemm_kernel,
                         cudaFuncAttributeMaxDynamicSharedMemorySize, SMEM_TOTAL);
    gemm_kernel<<<(M_TOTAL / BM) * (N_TOTAL / BN), THREADS, SMEM_TOTAL>>>(out, bias);
}

// round 15
// speedup vs baseline: 1.2180x; 1.2070x over previous
#include <cuda_runtime.h>
#include <cuda_fp16.h>
#include <cstdint>
#include <cstddef>

// ============================================================================
// FP4SymmetricLinear: C[8192,4096] = X[8192,4096] @ W^T[4096,4096] + bias
//
// compute_103 toolchain (no tcgen05). HMMA mma.sync path:
//   1) prepass: x fp32->fp16 AND fp4 dequant -> fp16 (single merged launch)
//   2) GEMM: 128x128 CTA tile, 4 warps (2Mx2N), warp tile 64x64, BK=64,
//      3-stage cp.async pipeline with SW128 XOR-swizzled SMEM (128B rows,
//      98,304 B/CTA -> 2 CTAs/SM), one __syncthreads per 64-wide K step,
//      mma.sync.m16n8k16 fp32 accum, bias epilogue.
// ============================================================================

#define M_TOTAL 8192
#define N_TOTAL 4096
#define K_TOTAL 4096

#define BM 128
#define BN 128
#define BK 64
#define KITERS (K_TOTAL / BK)       // 64
#define STAGES 3
#define THREADS 128

// Native 128B rows (64 halves = BK), SW128 XOR swizzle: 16B chunk index
// within the row is XORed with (row & 7). Conflict-free for cp.async 16B
// stores and ldmatrix reads.
#define ROW_BYTES   128
#define A_TILE_SMEM (BM * ROW_BYTES)             // 16384
#define B_TILE_SMEM (BN * ROW_BYTES)             // 16384
#define STAGE_SMEM  (A_TILE_SMEM + B_TILE_SMEM)  // 32768
#define SMEM_TOTAL  (STAGES * STAGE_SMEM)        // 98304 (x2 CTAs = 196.6KB)

// swizzled byte offset of (row, 16B-chunk) within a tile
#define SWZ(row, chunk) ((row) * ROW_BYTES + (((chunk) ^ ((row) & 7)) << 4))

// Scratch (device globals: allocation-free rule compliant)
__device__ __align__(16) __half g_x16[(size_t)M_TOTAL * K_TOTAL];
__device__ __align__(16) __half g_w16[(size_t)N_TOTAL * K_TOTAL];

__device__ __constant__ float c_codebook[16] = {
    0.0f, 0.0052f, 0.6667f, 1.0f, 0.3333f, 0.5f, 0.1667f, 0.25f,
    0.0f, -0.0052f, -0.6667f, -1.0f, -0.3333f, -0.5f, -0.1667f, -0.25f
};

// ---------------------------------------------------------------------------
// PTX helpers (compute_80-era instructions only — valid at compute_103)
// ---------------------------------------------------------------------------
__device__ __forceinline__ uint32_t smem_to_u32(const void* smem_ptr) {
    uint32_t addr;
    asm("{ .reg .u64 tmp; cvta.to.shared.u64 tmp, %1; cvt.u32.u64 %0, tmp; }"
        : "=r"(addr) : "l"(smem_ptr));
    return addr;
}

#define CP_ASYNC_CG(saddr, gptr) \
    asm volatile("cp.async.cg.shared.global [%0], [%1], 16;" \
                 :: "r"(saddr), "l"(gptr) : "memory")
#define CP_COMMIT() \
    asm volatile("cp.async.commit_group;" ::: "memory")
#define CP_WAIT(n) \
    asm volatile("cp.async.wait_group %0;" :: "n"(n) : "memory")

#define LDMATRIX_X4(r0, r1, r2, r3, addr) \
    asm volatile("ldmatrix.sync.aligned.m8n8.x4.shared.b16 {%0,%1,%2,%3}, [%4];" \
                 : "=r"(r0), "=r"(r1), "=r"(r2), "=r"(r3) : "r"(addr))

#define MMA16816(d, a, b) \
    asm volatile("mma.sync.aligned.m16n8k16.row.col.f32.f16.f16.f32 " \
                 "{%0,%1,%2,%3}, {%4,%5,%6,%7}, {%8,%9}, {%0,%1,%2,%3};" \
                 : "+f"((d)[0]), "+f"((d)[1]), "+f"((d)[2]), "+f"((d)[3]) \
                 : "r"((a)[0]), "r"((a)[1]), "r"((a)[2]), "r"((a)[3]), \
                   "r"((b)[0]), "r"((b)[1]))

// ---------------------------------------------------------------------------
// Merged prepass: blocks [0, 16384) convert x fp32->fp16 (8 elems/thread);
// blocks [16384, 24576) dequant packed fp4 -> fp16 (8 weights/thread).
// ---------------------------------------------------------------------------
__global__ void __launch_bounds__(256) prepass_kernel(
    const float4* __restrict__ x4,
    const int4* __restrict__ wp4,
    const float* __restrict__ scale
) {
    if (blockIdx.x < 16384) {
        size_t i = (size_t)blockIdx.x * 256 + threadIdx.x;   // 4,194,304 threads
        float4 a = x4[2 * i];
        float4 b = x4[2 * i + 1];
        union { uint4 u; __half2 h[4]; } t;
        t.h[0] = __floats2half2_rn(a.x, a.y);
        t.h[1] = __floats2half2_rn(a.z, a.w);
        t.h[2] = __floats2half2_rn(b.x, b.y);
        t.h[3] = __floats2half2_rn(b.z, b.w);
        ((uint4*)g_x16)[i] = t.u;
    } else {
        __shared__ float cb[16];
        if (threadIdx.x < 16) cb[threadIdx.x] = c_codebook[threadIdx.x];
        __syncthreads();

        size_t i = (size_t)(blockIdx.x - 16384) * 256 + threadIdx.x; // 2,097,152
        int4 p = wp4[i];
        float s = __ldg(scale + (i >> 3));
        union { uint4 u; __half h[8]; } t;
        t.h[0] = __float2half_rn(cb[(p.x >> 4) & 15] * s);
        t.h[1] = __float2half_rn(cb[p.x & 15] * s);
        t.h[2] = __float2half_rn(cb[(p.y >> 4) & 15] * s);
        t.h[3] = __float2half_rn(cb[p.y & 15] * s);
        t.h[4] = __float2half_rn(cb[(p.z >> 4) & 15] * s);
        t.h[5] = __float2half_rn(cb[p.z & 15] * s);
        t.h[6] = __float2half_rn(cb[(p.w >> 4) & 15] * s);
        t.h[7] = __float2half_rn(cb[p.w & 15] * s);
        ((uint4*)g_w16)[i] = t.u;
    }
}

// ---------------------------------------------------------------------------
// GEMM kernel
// 4 warps: 2 (M) x 2 (N); warp tile 64x64; per-thread 4x8 m16n8 accumulators.
// BK=64 (4 k16 chunks), 3-stage swizzled SMEM pipeline, 1 sync per K step.
// ---------------------------------------------------------------------------
__global__ void __launch_bounds__(THREADS, 2) gemm_kernel(
    float* __restrict__ out, const float* __restrict__ bias
) {
    extern __shared__ char smem[];
    uint32_t smem_u32 = smem_to_u32(smem);
    int tid  = threadIdx.x;
    int wid  = tid >> 5;
    int lane = tid & 31;
    int wm   = wid & 1;          // warp row 0..1 (64 M-rows each)
    int wn   = wid >> 1;         // warp col 0..1 (64 N-cols each)

    // Rasterize: supertiles of 8 M-tiles x all 32 N-tiles for L2 reuse
    int pid = blockIdx.x;                 // 0..2047
    int g   = pid >> 8;                   // 8 groups
    int rem = pid & 255;
    int mt  = (g << 3) + (rem & 7);       // 0..63
    int nt  = rem >> 3;                   // 0..31
    int m0  = mt * BM;
    int n0  = nt * BN;

    const __half* __restrict__ xA = g_x16 + (size_t)m0 * K_TOTAL;
    const __half* __restrict__ wB = g_w16 + (size_t)n0 * K_TOTAL;

    // Load coords: 16B chunks; tile = 128 rows x 8 chunks = 1024 chunks;
    // 8 chunks/thread per operand. Rows: lr + it*16, fixed chunk lc.
    int lr = tid >> 3, lc = tid & 7;

    auto issue_stage = [&](int s) {
        int kpos = s * BK;
        uint32_t sbase = smem_u32 + (s % STAGES) * STAGE_SMEM;
        uint32_t bb = sbase + A_TILE_SMEM;
        #pragma unroll
        for (int it = 0; it < 8; ++it) {
            int r = lr + it * 16;
            uint32_t off = SWZ(r, lc);
            CP_ASYNC_CG(sbase + off,
                        xA + (size_t)r * K_TOTAL + kpos + lc * 8);
            CP_ASYNC_CG(bb + off,
                        wB + (size_t)r * K_TOTAL + kpos + lc * 8);
        }
        CP_COMMIT();
    };

    float acc[4][8][4];
    #pragma unroll
    for (int i = 0; i < 4; ++i)
        #pragma unroll
        for (int j = 0; j < 8; ++j)
            #pragma unroll
            for (int k = 0; k < 4; ++k) acc[i][j][k] = 0.0f;

    issue_stage(0);
    issue_stage(1);

    // ldmatrix lane addressing
    int a_row_l   = lane & 15;             // row within 16x16 A tile
    int a_chunk_l = lane >> 4;             // k16-half -> 16B chunk offset
    int b_mat     = lane >> 3;             // which 8x8 matrix
    int b_row_l   = (lane & 7) + ((b_mat >> 1) << 3);
    int b_chunk_l = b_mat & 1;

    for (int s = 0; s < KITERS; ++s) {
        // Wait for stage s (leaves <=1 group pending = stage s+1).
        CP_WAIT(1);
        __syncthreads();

        // Buffer (s+2)%3 == (s-1)%3 drained last iteration -> refill.
        if (s + 2 < KITERS) issue_stage(s + 2);
        else CP_COMMIT();   // keep wait_group counting aligned

        uint32_t sbase = smem_u32 + (s % STAGES) * STAGE_SMEM;
        uint32_t aBase = sbase;
        uint32_t bBase = sbase + A_TILE_SMEM;

        #pragma unroll
        for (int ks = 0; ks < 4; ++ks) {       // 4 x k16 per BK=64
            uint32_t a[4][4];
            uint32_t b[8][2];
            #pragma unroll
            for (int mi = 0; mi < 4; ++mi) {
                int row = wm * 64 + mi * 16 + a_row_l;
                LDMATRIX_X4(a[mi][0], a[mi][1], a[mi][2], a[mi][3],
                            aBase + SWZ(row, ks * 2 + a_chunk_l));
            }
            #pragma unroll
            for (int j = 0; j < 4; ++j) {
                int nrow = wn * 64 + j * 16 + b_row_l;
                LDMATRIX_X4(b[2 * j][0], b[2 * j][1],
                            b[2 * j + 1][0], b[2 * j + 1][1],
                            bBase + SWZ(nrow, ks * 2 + b_chunk_l));
            }
            #pragma unroll
            for (int mi = 0; mi < 4; ++mi)
                #pragma unroll
                for (int nj = 0; nj < 8; ++nj)
                    MMA16816(acc[mi][nj], a[mi], b[nj]);
        }
    }

    // Epilogue: m16n8 D frag: d0,d1 -> row l>>2, cols 2(l&3)+{0,1};
    // d2,d3 -> row (l>>2)+8.
    int row_base = m0 + wm * 64 + (lane >> 2);
    int col_base = n0 + wn * 64 + (lane & 3) * 2;
    #pragma unroll
    for (int mi = 0; mi < 4; ++mi) {
        #pragma unroll
        for (int nj = 0; nj < 8; ++nj) {
            int c = col_base + nj * 8;
            float2 bv = *(const float2*)(bias + c);
            #pragma unroll
            for (int h = 0; h < 2; ++h) {
                int r = row_base + mi * 16 + h * 8;
                float2 o;
                o.x = acc[mi][nj][2 * h + 0] + bv.x;
                o.y = acc[mi][nj][2 * h + 1] + bv.y;
                *(float2*)(out + (size_t)r * N_TOTAL + c) = o;
            }
        }
    }
}

// ---------------------------------------------------------------------------
// Launch
// ---------------------------------------------------------------------------
extern "C" void kernel_launch(void* const* d_in, const int* in_sizes, int n_in,
                              void* d_out, int out_size) {
    const float* x     = (const float*)d_in[0];   // [4,2048,4096] fp32
    const int*   wp    = (const int*)d_in[1];     // [8388608] int32 (1 byte each)
    const float* scale = (const float*)d_in[2];   // [262144] fp32
    const float* bias  = (const float*)d_in[3];   // [4096] fp32
    float*       out   = (float*)d_out;           // [4,2048,4096] fp32

    (void)in_sizes; (void)n_in; (void)out_size;

    prepass_kernel<<<24576, 256>>>((const float4*)x, (const int4*)wp, scale);

    cudaFuncSetAttribute(gemm_kernel,
                         cudaFuncAttributeMaxDynamicSharedMemorySize, SMEM_TOTAL);
    gemm_kernel<<<(M_TOTAL / BM) * (N_TOTAL / BN), THREADS, SMEM_TOTAL>>>(out, bias);
}